// round 2
// baseline (speedup 1.0000x reference)
#include <cuda_runtime.h>
#include <math.h>

#define BM 128
#define BN 128
#define BK 16

// Scratch: code-usage histogram (K=30 <= 32). __device__ global per allocation rules.
__device__ int g_hist[32];

__device__ __forceinline__ unsigned long long pack_dup(float a) {
    unsigned long long r;
    unsigned int u = __float_as_uint(a);
    asm("mov.b64 %0, {%1, %1};" : "=l"(r) : "r"(u));
    return r;
}

__device__ __forceinline__ void ffma2(unsigned long long& d, unsigned long long a,
                                      unsigned long long b) {
    // packed fp32x2 FMA: two independent fp32 FMAs per instruction (sm_103a)
    asm("fma.rn.f32x2 %0, %1, %2, %0;" : "+l"(d) : "l"(a), "l"(b));
}

__global__ void init_hist_kernel() {
    if (threadIdx.x < 32) g_hist[threadIdx.x] = 0;
}

__global__ __launch_bounds__(256, 2)
void fused_gemm_vq_kernel(
    const float* __restrict__ s0g, const float* __restrict__ s1g,
    const float* __restrict__ W0g, const float* __restrict__ b0g,
    const float* __restrict__ W1g, const float* __restrict__ b1g,
    const float* __restrict__ Wfg, const float* __restrict__ bfg,
    const float* __restrict__ cbg,
    float* __restrict__ out,
    int N, int D, int K)
{
    extern __shared__ float smem[];
    float* As = smem;                 // [2][BK][BM]  (transposed A: As[k][m])
    float* Bs = smem + 2 * BK * BM;   // [2][BK][BN]

    const int tid = threadIdx.x;
    const int tx  = tid & 15;         // 0..15  -> col group (8 cols)
    const int ty  = tid >> 4;         // 0..15  -> row group (8 rows)
    const int m0  = blockIdx.x * BM;

    // global-load mapping
    const int lrow  = tid >> 2;         // 0..63 (A rows, +64 for second half)
    const int lcol4 = (tid & 3) * 4;    // 0..12 (A k-offset, float4)
    const int brow  = tid >> 5;         // 0..7  (B k row, +8 for second half)
    const int bcol  = (tid & 31) * 4;   // 0..124 (B col, float4)

    // 8 rows x 4 col-pairs of packed fp32x2 accumulators
    unsigned long long acc[8][4];
#pragma unroll
    for (int i = 0; i < 8; ++i)
#pragma unroll
        for (int j = 0; j < 4; ++j) acc[i][j] = 0ull;

    int buf = 0;
    const int nk = D / BK;

    for (int phase = 0; phase < 2; ++phase) {
        const float* Ag = phase ? s1g : s0g;
        const float* Bg = phase ? W1g : W0g;

        // load first tile into current buffer
        {
            float4 a0 = *(const float4*)(Ag + (size_t)(m0 + lrow) * D + lcol4);
            float4 a1 = *(const float4*)(Ag + (size_t)(m0 + lrow + 64) * D + lcol4);
            float4 w0 = *(const float4*)(Bg + (size_t)brow * BN + bcol);
            float4 w1 = *(const float4*)(Bg + (size_t)(brow + 8) * BN + bcol);
            float* Asb = As + buf * (BK * BM);
            Asb[(lcol4 + 0) * BM + lrow]      = a0.x;
            Asb[(lcol4 + 1) * BM + lrow]      = a0.y;
            Asb[(lcol4 + 2) * BM + lrow]      = a0.z;
            Asb[(lcol4 + 3) * BM + lrow]      = a0.w;
            Asb[(lcol4 + 0) * BM + lrow + 64] = a1.x;
            Asb[(lcol4 + 1) * BM + lrow + 64] = a1.y;
            Asb[(lcol4 + 2) * BM + lrow + 64] = a1.z;
            Asb[(lcol4 + 3) * BM + lrow + 64] = a1.w;
            float* Bsb = Bs + buf * (BK * BN);
            *(float4*)(Bsb + brow * BN + bcol)       = w0;
            *(float4*)(Bsb + (brow + 8) * BN + bcol) = w1;
        }
        __syncthreads();

        for (int kt = 0; kt < nk; ++kt) {
            float4 pa0, pa1, pw0, pw1;
            const bool has_next = (kt + 1 < nk);
            if (has_next) {
                const float* Ap = Ag + (size_t)(m0 + lrow) * D + (kt + 1) * BK + lcol4;
                pa0 = *(const float4*)Ap;
                pa1 = *(const float4*)(Ap + (size_t)64 * D);
                const float* Bp = Bg + (size_t)((kt + 1) * BK + brow) * BN + bcol;
                pw0 = *(const float4*)Bp;
                pw1 = *(const float4*)(Bp + 8 * BN);
            }
            const float* Asb = As + buf * (BK * BM);
            const float* Bsb = Bs + buf * (BK * BN);
#pragma unroll
            for (int k = 0; k < BK; ++k) {
                float4 av0 = *(const float4*)(Asb + k * BM + ty * 8);
                float4 av1 = *(const float4*)(Asb + k * BM + ty * 8 + 4);
                ulonglong2 bp0 = *(const ulonglong2*)(Bsb + k * BN + tx * 8);
                ulonglong2 bp1 = *(const ulonglong2*)(Bsb + k * BN + tx * 8 + 4);
                unsigned long long bb0 = bp0.x, bb1 = bp0.y, bb2 = bp1.x, bb3 = bp1.y;
                float aa[8] = {av0.x, av0.y, av0.z, av0.w, av1.x, av1.y, av1.z, av1.w};
#pragma unroll
                for (int i = 0; i < 8; ++i) {
                    unsigned long long ad = pack_dup(aa[i]);
                    ffma2(acc[i][0], ad, bb0);
                    ffma2(acc[i][1], ad, bb1);
                    ffma2(acc[i][2], ad, bb2);
                    ffma2(acc[i][3], ad, bb3);
                }
            }
            if (has_next) {
                float* Asb2 = As + (buf ^ 1) * (BK * BM);
                Asb2[(lcol4 + 0) * BM + lrow]      = pa0.x;
                Asb2[(lcol4 + 1) * BM + lrow]      = pa0.y;
                Asb2[(lcol4 + 2) * BM + lrow]      = pa0.z;
                Asb2[(lcol4 + 3) * BM + lrow]      = pa0.w;
                Asb2[(lcol4 + 0) * BM + lrow + 64] = pa1.x;
                Asb2[(lcol4 + 1) * BM + lrow + 64] = pa1.y;
                Asb2[(lcol4 + 2) * BM + lrow + 64] = pa1.z;
                Asb2[(lcol4 + 3) * BM + lrow + 64] = pa1.w;
                float* Bsb2 = Bs + (buf ^ 1) * (BK * BN);
                *(float4*)(Bsb2 + brow * BN + bcol)       = pw0;
                *(float4*)(Bsb2 + (brow + 8) * BN + bcol) = pw1;
            }
            __syncthreads();
            buf ^= 1;
        }
    }

    // ---- epilogue: x = relu(acc + b0 + b1) -> smem (stride 129, conflict-free) ----
    float* xs = smem;  // reuse: 128 * 129 floats = 66048 B
#pragma unroll
    for (int j = 0; j < 4; ++j) {
        const int c = tx * 8 + 2 * j;
        const float bias0 = __ldg(b0g + c)     + __ldg(b1g + c);
        const float bias1 = __ldg(b0g + c + 1) + __ldg(b1g + c + 1);
#pragma unroll
        for (int i = 0; i < 8; ++i) {
            unsigned long long v = acc[i][j];
            float x0 = __uint_as_float((unsigned int)(v & 0xffffffffull));
            float x1 = __uint_as_float((unsigned int)(v >> 32));
            x0 = fmaxf(x0 + bias0, 0.0f);
            x1 = fmaxf(x1 + bias1, 0.0f);
            const int r = ty * 8 + i;
            xs[r * 129 + c]     = x0;
            xs[r * 129 + c + 1] = x1;
        }
    }
    __syncthreads();

    // ---- per-row: flat = x @ Wf + bf (fp64 accumulated, rounded to fp32 once),
    //      then VQ argmin with the reference's exact fp32 distance expansion ----
    if (tid < BM) {
        const int row = tid;
        const float* xr = xs + row * 129;
        double F0 = 0.0, F1 = 0.0, F2 = 0.0, F3 = 0.0;
#pragma unroll 8
        for (int h = 0; h < 128; ++h) {
            const double xv = (double)xr[h];
            F0 = fma(xv, (double)__ldg(Wfg + h * 4 + 0), F0);
            F1 = fma(xv, (double)__ldg(Wfg + h * 4 + 1), F1);
            F2 = fma(xv, (double)__ldg(Wfg + h * 4 + 2), F2);
            F3 = fma(xv, (double)__ldg(Wfg + h * 4 + 3), F3);
        }
        // single rounding to fp32 -> essentially correctly-rounded flat
        const float f0 = (float)(F0 + (double)__ldg(bfg + 0));
        const float f1 = (float)(F1 + (double)__ldg(bfg + 1));
        const float f2 = (float)(F2 + (double)__ldg(bfg + 2));
        const float f3 = (float)(F3 + (double)__ldg(bfg + 3));

        // reference: d = sum(flat*flat) + sum(cb*cb) - 2*flat@cb.T, fp32-rounded
        const float ff = ((f0 * f0 + f1 * f1) + f2 * f2) + f3 * f3;
        float dmin = 3.4e38f;
        int best = 0;
        for (int k = 0; k < K; ++k) {
            const float c0 = __ldg(cbg + k * 4 + 0), c1 = __ldg(cbg + k * 4 + 1);
            const float c2 = __ldg(cbg + k * 4 + 2), c3 = __ldg(cbg + k * 4 + 3);
            const float cc  = ((c0 * c0 + c1 * c1) + c2 * c2) + c3 * c3;
            const float dot = ((f0 * c0 + f1 * c1) + f2 * c2) + f3 * c3;
            const float t   = ff + cc;
            const float dk  = t - 2.0f * dot;
            if (dk < dmin) { dmin = dk; best = k; }  // strict < == jnp.argmin first-min
        }

        const int gr = m0 + row;
        const float c0 = __ldg(cbg + best * 4 + 0), c1 = __ldg(cbg + best * 4 + 1);
        const float c2 = __ldg(cbg + best * 4 + 2), c3 = __ldg(cbg + best * 4 + 3);
        const size_t zbase = (size_t)gr * 4;
        // straight-through z = flat + (quantized - flat), fp32 like reference
        out[zbase + 0] = f0 + (c0 - f0);
        out[zbase + 1] = f1 + (c1 - f1);
        out[zbase + 2] = f2 + (c2 - f2);
        out[zbase + 3] = f3 + (c3 - f3);
        // loss from direct diffs like the reference loss path:
        // m = mean((q-f)^2); loss = m + 1.0*m
        const float d0 = c0 - f0, d1 = c1 - f1, d2 = c2 - f2, d3 = c3 - f3;
        float m = ((d0 * d0 + d1 * d1) + d2 * d2) + d3 * d3;
        m *= 0.25f;
        const size_t zlen = (size_t)N * 4;
        out[zlen + gr] = m + m;
        out[zlen + (size_t)N + 1 + gr] = (float)best;  // idx (after perplexity scalar)
        atomicAdd(&g_hist[best], 1);
    }
}

__global__ void finalize_kernel(float* __restrict__ out, int N, int K) {
    if (threadIdx.x == 0) {
        const float invN = 1.0f / (float)N;
        float s = 0.0f;
        for (int k = 0; k < K; ++k) {
            const float p = (float)g_hist[k] * invN;
            s += p * logf(p + 1e-10f);
        }
        out[(size_t)N * 4 + N] = expf(-s);  // perplexity
    }
}

extern "C" void kernel_launch(void* const* d_in, const int* in_sizes, int n_in,
                              void* d_out, int out_size) {
    const float* s0 = (const float*)d_in[0];
    const float* s1 = (const float*)d_in[1];
    const float* W0 = (const float*)d_in[2];
    const float* b0 = (const float*)d_in[3];
    const float* W1 = (const float*)d_in[4];
    const float* b1 = (const float*)d_in[5];
    const float* Wf = (const float*)d_in[6];
    const float* bf = (const float*)d_in[7];
    const float* cb = (const float*)d_in[8];
    float* out = (float*)d_out;

    const int H = in_sizes[3];         // 128
    const int E = in_sizes[7];         // 4
    const int K = in_sizes[8] / E;     // 30
    const int D = in_sizes[2] / H;     // 4096
    const int N = in_sizes[0] / D;     // 32768

    const int smem_bytes = 128 * 129 * (int)sizeof(float);  // 66048 (epilogue superset)
    cudaFuncSetAttribute(fused_gemm_vq_kernel,
                         cudaFuncAttributeMaxDynamicSharedMemorySize, smem_bytes);

    init_hist_kernel<<<1, 32>>>();
    fused_gemm_vq_kernel<<<N / BM, 256, smem_bytes>>>(s0, s1, W0, b0, W1, b1,
                                                      Wf, bf, cb, out, N, D, K);
    finalize_kernel<<<1, 32>>>(out, N, K);
}